// round 6
// baseline (speedup 1.0000x reference)
#include <cuda_runtime.h>
#include <cstdint>
#include <cstddef>

// ---------------------------------------------------------------------------
// ColorHistogramMatchingLoss
//   hist[b,c][i][j] = sum_n w_n * rbf(u_n)[i] * rbf(v_n)[j]   (64x64xN GEMM)
//   loss = mean_b sqrt(0.5 * sum (sqrt(hy/ty) - sqrt(hx/tx))^2)
//
// R5: single-wave grid (288 blocks), A stored duplicated in smem so packed
// f32x2 operands load directly (zero MOVs), fill (MUFU) software-pipelined
// into the GEMM (FMA) with one barrier per chunk, finalize fused via
// completion counter (2 launches per call).
// ---------------------------------------------------------------------------

#define D_HIST   64
#define CHUNK    64
#define SPLITS   6
#define PX_PER_SPLIT 10923            // ceil(65536/6)
#define NCHUNKS  171                  // ceil(10923/64)
#define HIST_BLOCKS (2*8*3*SPLITS)    // 288  (<= 296 slots: single wave)
#define EPS_F    1e-6f
#define PLANE    65536
#define HTOT     (2*8*3*D_HIST*D_HIST)

__device__ float    g_hist[HTOT];
__device__ unsigned g_done;

// double-buffered staging (dynamic smem, 99840 B per block)
struct SmemLayout {
    float A2[2][CHUNK][2*D_HIST];   // duplicated pairs: A2[k][2i]=A2[k][2i+1]=w*rbf_u
    float B [2][CHUNK][D_HIST];     // rbf_v
    float u [2][CHUNK];
    float v [2][CHUNK];
    float w [2][CHUNK];
};

// ---- packed f32x2 + vector shared access (sm_103a) ------------------------
__device__ __forceinline__ void fma2(unsigned long long &d,
                                     unsigned long long a,
                                     unsigned long long b) {
    asm("fma.rn.f32x2 %0, %1, %2, %0;" : "+l"(d) : "l"(a), "l"(b));
}
__device__ __forceinline__ void lds_pair(unsigned long long &a,
                                         unsigned long long &b, unsigned addr) {
    asm volatile("ld.shared.v2.u64 {%0, %1}, [%2];"
                 : "=l"(a), "=l"(b) : "r"(addr));
}
__device__ __forceinline__ void sts_dup(unsigned addr, float v) {
    asm volatile("st.shared.v2.f32 [%0], {%1, %1};" :: "r"(addr), "f"(v));
}

// ---------------------------------------------------------------------------
__global__ void zero_kernel() {
    int i = blockIdx.x * blockDim.x + threadIdx.x;
    if (i < HTOT) g_hist[i] = 0.0f;
    if (i == 0) g_done = 0u;
}

// ---------------------------------------------------------------------------
__global__ __launch_bounds__(256, 2)
void hist_kernel(const float* __restrict__ x, const float* __restrict__ y,
                 float* __restrict__ out)
{
    extern __shared__ char smem_raw[];
    SmemLayout* S = reinterpret_cast<SmemLayout*>(smem_raw);

    const int bx     = blockIdx.x;
    const int split  = bx % SPLITS;
    const int r1     = bx / SPLITS;
    const int c      = r1 % 3;
    const int r2     = r1 / 3;
    const int b      = r2 & 7;
    const int tensor = r2 >> 3;
    const float* img = (tensor ? y : x) + (size_t)b * 3u * PLANE;

    const int base = split * PX_PER_SPLIT;
    const int pend = min(base + PX_PER_SPLIT, PLANE);

    const int   t    = threadIdx.x;
    const int   lcol = t & 63;                 // bin column in fill phase
    const int   sel  = t >> 6;                 // 0..3
    const float cs   = fmaf((float)lcol, 300.0f/63.0f, -150.0f); // 50*center
    const int   i0   = ((t & 63) >> 3) * 8;    // GEMM tile row base
    const int   j0   = (t & 7) * 8;            // GEMM tile col base
    const int   kbase = sel * 16;              // GEMM k-slice for this group
    const int   fk0   = (sel & 1) * 32;        // fill k-offset
    const bool  isA   = sel < 2;               // fill role (uniform per warp)

    unsigned long long acc[8][4];
    #pragma unroll
    for (int i = 0; i < 8; i++)
        #pragma unroll
        for (int j = 0; j < 4; j++) acc[i][j] = 0ull;

    const unsigned sm = (unsigned)__cvta_generic_to_shared(S);
    const unsigned A2b = sm;            // + buf*32768 + k*512 + col*8
    const unsigned Bb  = sm + 65536u;   // + buf*16384 + k*256 + col*4

    // ---- helpers ----------------------------------------------------------
    auto load_raw = [&](int chk, float &rr, float &gg, float &bb_) {
        int p = base + chk * CHUNK + t;
        bool valid = p < pend;
        rr  = valid ? img[p]             : 1.0f;
        gg  = valid ? img[PLANE + p]     : 1.0f;
        bb_ = valid ? img[2*PLANE + p]   : 1.0f;
    };
    auto prepass = [&](int buf, int chk, float rr, float gg, float bb_) {
        int p = base + chk * CHUNK + t;
        bool valid = p < pend;
        rr += EPS_F; gg += EPS_F; bb_ += EPS_F;
        float lr = logf(rr), lg = logf(gg), lb = logf(bb_);
        float a = lr - lg, d2 = lr - lb;     // ur, vr
        float uu, vv;
        if (c == 0)      { uu =  a;  vv = d2;     }
        else if (c == 1) { uu = -a;  vv = d2 - a; }
        else             { uu = -d2; vv = a - d2; }
        S->u[buf][t] = uu * 50.0f;
        S->v[buf][t] = vv * 50.0f;
        S->w[buf][t] = valid ? sqrtf(fmaf(rr, rr, fmaf(gg, gg, bb_*bb_))) : 0.0f;
    };
    auto fill_one = [&](int buf, int f) {
        int k = fk0 + f;
        if (isA) {
            float tt  = S->u[buf][k] - cs;
            float den = fmaf(tt, tt, 1.0f);
            float val = __fdividef(S->w[buf][k], den);
            sts_dup(A2b + (unsigned)buf*32768u + (unsigned)k*512u + (unsigned)lcol*8u, val);
        } else {
            float tt  = S->v[buf][k] - cs;
            float den = fmaf(tt, tt, 1.0f);
            S->B[buf][k][lcol] = __fdividef(1.0f, den);
        }
    };

    // ---- prologue: uvw[0],uvw[1]; fill chunk0; raw chunk2 in regs ---------
    float pr = 1.0f, pg = 1.0f, pb_ = 1.0f;
    if (t < CHUNK) {
        load_raw(0, pr, pg, pb_);  prepass(0, 0, pr, pg, pb_);
        load_raw(1, pr, pg, pb_);  prepass(1, 1, pr, pg, pb_);
    }
    __syncthreads();
    #pragma unroll 4
    for (int f = 0; f < 32; f++) fill_one(0, f);
    if (t < CHUNK) load_raw(2, pr, pg, pb_);
    __syncthreads();

    // ---- main pipeline: ONE barrier per chunk -----------------------------
    // body n: prepass(n+2)->uvw[cur], LDG(n+3)->regs,
    //         interleave { fill(n+1)->bufs[nxt] , GEMM(n)<-bufs[cur] }
    #define GEMM_STEP do {                                                   \
        unsigned long long p0,p1,p2,p3,p4,p5,p6,p7, q0,q1,q2,q3;             \
        lds_pair(p0, p1, aA);        lds_pair(p2, p3, aA + 16u);             \
        lds_pair(p4, p5, aA + 32u);  lds_pair(p6, p7, aA + 48u);             \
        lds_pair(q0, q1, aB);        lds_pair(q2, q3, aB + 16u);             \
        fma2(acc[0][0],p0,q0); fma2(acc[0][1],p0,q1); fma2(acc[0][2],p0,q2); fma2(acc[0][3],p0,q3); \
        fma2(acc[1][0],p1,q0); fma2(acc[1][1],p1,q1); fma2(acc[1][2],p1,q2); fma2(acc[1][3],p1,q3); \
        fma2(acc[2][0],p2,q0); fma2(acc[2][1],p2,q1); fma2(acc[2][2],p2,q2); fma2(acc[2][3],p2,q3); \
        fma2(acc[3][0],p3,q0); fma2(acc[3][1],p3,q1); fma2(acc[3][2],p3,q2); fma2(acc[3][3],p3,q3); \
        fma2(acc[4][0],p4,q0); fma2(acc[4][1],p4,q1); fma2(acc[4][2],p4,q2); fma2(acc[4][3],p4,q3); \
        fma2(acc[5][0],p5,q0); fma2(acc[5][1],p5,q1); fma2(acc[5][2],p5,q2); fma2(acc[5][3],p5,q3); \
        fma2(acc[6][0],p6,q0); fma2(acc[6][1],p6,q1); fma2(acc[6][2],p6,q2); fma2(acc[6][3],p6,q3); \
        fma2(acc[7][0],p7,q0); fma2(acc[7][1],p7,q1); fma2(acc[7][2],p7,q2); fma2(acc[7][3],p7,q3); \
        aA += 512u; aB += 256u;                                              \
    } while (0)

    for (int n = 0; n < NCHUNKS; n++) {
        const int cur = n & 1, nxt = cur ^ 1;

        if (t < CHUNK && n + 2 < NCHUNKS) prepass(cur, n + 2, pr, pg, pb_);
        if (t < CHUNK && n + 3 < NCHUNKS) load_raw(n + 3, pr, pg, pb_);

        unsigned aA = A2b + (unsigned)cur*32768u + (unsigned)kbase*512u + (unsigned)i0*8u;
        unsigned aB = Bb  + (unsigned)cur*16384u + (unsigned)kbase*256u + (unsigned)j0*4u;

        if (n + 1 < NCHUNKS) {
            #pragma unroll
            for (int kk = 0; kk < 16; kk++) {
                fill_one(nxt, 2*kk);
                fill_one(nxt, 2*kk + 1);
                GEMM_STEP;
            }
        } else {
            #pragma unroll
            for (int kk = 0; kk < 16; kk++) GEMM_STEP;
        }
        __syncthreads();
    }
    #undef GEMM_STEP

    // ---- combine 4 k-group partials in shared, then RED.global -----------
    float* Csh = reinterpret_cast<float*>(smem_raw);   // reuse A2 region
    for (int i = t; i < D_HIST * D_HIST; i += 256) Csh[i] = 0.0f;
    __syncthreads();
    #pragma unroll
    for (int ii = 0; ii < 8; ii++) {
        #pragma unroll
        for (int jj = 0; jj < 4; jj++) {
            unsigned long long v2 = acc[ii][jj];
            float lo = __uint_as_float((unsigned)(v2 & 0xffffffffull));
            float hi = __uint_as_float((unsigned)(v2 >> 32));
            atomicAdd(&Csh[(i0 + ii) * D_HIST + j0 + 2*jj    ], lo);
            atomicAdd(&Csh[(i0 + ii) * D_HIST + j0 + 2*jj + 1], hi);
        }
    }
    __syncthreads();
    float* dst = g_hist + (size_t)(((tensor * 8) + b) * 3 + c) * (D_HIST * D_HIST);
    for (int i = t; i < D_HIST * D_HIST; i += 256) atomicAdd(&dst[i], Csh[i]);

    // ---- fused finalize: last block does the reduction --------------------
    __threadfence();
    __shared__ unsigned s_last;
    if (t == 0) s_last = (atomicAdd(&g_done, 1u) == (unsigned)(HIST_BLOCKS - 1));
    __syncthreads();
    if (!s_last) return;

    __shared__ float s_red[8];
    __shared__ float s_inv[16];
    __shared__ float s_loss;
    const int lane = t & 31, wp = t >> 5;
    const int PER_B = 3 * D_HIST * D_HIST;     // 12288
    if (t == 0) s_loss = 0.0f;

    for (int g = 0; g < 16; g++) {             // totals (8 x-hists, 8 y-hists)
        const float* h = g_hist + (size_t)g * PER_B;
        float ssum = 0.0f;
        for (int i = t; i < PER_B; i += 256) ssum += h[i];
        #pragma unroll
        for (int o = 16; o > 0; o >>= 1) ssum += __shfl_down_sync(0xffffffffu, ssum, o);
        if (lane == 0) s_red[wp] = ssum;
        __syncthreads();
        if (t == 0) {
            float v = 0.0f;
            #pragma unroll
            for (int j2 = 0; j2 < 8; j2++) v += s_red[j2];
            s_inv[g] = 1.0f / v;
        }
        __syncthreads();
    }

    for (int bb2 = 0; bb2 < 8; bb2++) {
        const float* hx = g_hist + (size_t)bb2 * PER_B;
        const float* hy = g_hist + (size_t)(8 + bb2) * PER_B;
        float ix = s_inv[bb2], iy = s_inv[8 + bb2];
        float a2 = 0.0f;
        for (int i = t; i < PER_B; i += 256) {
            float d = sqrtf(hy[i] * iy) - sqrtf(hx[i] * ix);
            a2 = fmaf(d, d, a2);
        }
        #pragma unroll
        for (int o = 16; o > 0; o >>= 1) a2 += __shfl_down_sync(0xffffffffu, a2, o);
        if (lane == 0) s_red[wp] = a2;
        __syncthreads();
        if (t == 0) {
            float v = 0.0f;
            #pragma unroll
            for (int j2 = 0; j2 < 8; j2++) v += s_red[j2];
            s_loss += sqrtf(v * 0.5f);
        }
        __syncthreads();
    }
    if (t == 0) out[0] = s_loss * 0.125f;
}

// ---------------------------------------------------------------------------
extern "C" void kernel_launch(void* const* d_in, const int* in_sizes, int n_in,
                              void* d_out, int out_size) {
    (void)in_sizes; (void)n_in; (void)out_size;
    const float* x = (const float*)d_in[0];
    const float* y = (const float*)d_in[1];

    cudaFuncSetAttribute((const void*)hist_kernel,
                         cudaFuncAttributeMaxDynamicSharedMemorySize,
                         (int)sizeof(SmemLayout));

    zero_kernel<<<(HTOT + 1023) / 1024, 1024>>>();
    hist_kernel<<<HIST_BLOCKS, 256, sizeof(SmemLayout)>>>(x, y, (float*)d_out);
}